// round 12
// baseline (speedup 1.0000x reference)
#include <cuda_runtime.h>
#include <math_constants.h>

// RoIPool, warp-cooperative, single-pass row scan, float2 lanes, CPW=8,
// depth-2 ring, unconditional clamped refills (proven cheaper than predication).
// feature [B,C,152,152] f32, rois [N,5] f32, out [N,C,7,7] f32.
// One warp = (roi n, 8 consecutive channels).
//   Columns: xs0 = xs & ~1, d = xs - xs0 (<=1). Half-warp hw covers channel
//   parity; channel group g=0..3 -> channel c0 + 2g + hw, all loaded from ONE
//   address register + constant byte offsets (g*2*23104*4 < 2MB imm range).
//   Lane ln loads float2 at pair min(ln, plim), plim=(d+roiw)>>1 <= 15: all
//   positions phase 2 reads (d..d+roiw <= 31) covered; tail lanes duplicate
//   the last pair (same cache lines, harmless for max).
//   Rows: scan ys..hlast = ys+ceil(7*binh)-1 once; bins tile with <=1-row
//   overlap; several bins may close on one row (do/while). Depth-2 register
//   ring, prefetch distance 2, refills clamped to hlast (duplicates never
//   stored: all 7 bins close by h=hlast, ph<7 guards the close).
// Bin sizes = roiX * fl(1/7) (reciprocal multiply) to match XLA bit-exactly.

#define PH 7
#define PW 7
#define HF 152
#define WF 152
#define CPW 8
#define WARPS 4
#define CS (HF * WF)          // channel stride in floats (compile-time const)

__global__ __launch_bounds__(128) void roipool_c8_kernel(
    const float* __restrict__ feat,
    const float* __restrict__ rois,
    const int* __restrict__ stride_p,
    float* __restrict__ out,
    int C, int gpr)
{
    __shared__ __align__(16) float rm[WARPS][CPW][PH][34];   // 30464 B

    int si = *stride_p;
    float stride_f = (si > 0 && si <= 65536) ? (float)si : __int_as_float(si);
    const float scale = 1.0f / stride_f;

    const int warpId = threadIdx.x >> 5;
    const int lane   = threadIdx.x & 31;
    const int hw = lane >> 4;          // channel parity
    const int ln = lane & 15;          // column pair
    const int wg = blockIdx.x * WARPS + warpId;
    const int n  = wg / gpr;
    const int cg = wg - n * gpr;
    const int c0 = cg * CPW;

    const float* r = rois + n * 5;
    const int b  = (int)r[0];
    const int xs = (int)rintf(r[1] * scale);   // round-half-even, matches jnp.round
    const int ys = (int)rintf(r[2] * scale);
    const int xe = (int)rintf(r[3] * scale);
    const int ye = (int)rintf(r[4] * scale);
    const int roih = max(ye - ys + 1, 1);
    const int roiw = max(xe - xs + 1, 1);
    const float binh = (float)roih * (1.0f / 7.0f);   // reciprocal multiply (bit-exact)
    const float binw = (float)roiw * (1.0f / 7.0f);

    const int xs0 = xs & ~1;
    const int d   = xs - xs0;
    const int plim = (d + roiw) >> 1;           // last pair phase 2 can touch (<=15)
    const int c2   = xs0 + 2 * min(ln, plim);   // in-bounds (<=150)

    // single base pointer (channel c0+hw); other channels via const offsets
    const float* fp = feat + ((size_t)(b * C + c0 + hw)) * (size_t)CS + c2;

    const int hlast = ys + (int)ceilf(7.0f * binh) - 1;   // <= ye+1 <= 151
    int ph   = 0;
    int hcut = ys + (int)ceilf(binh);                     // hend of bin 0

    const float2 NEG2 = make_float2(-CUDART_INF_F, -CUDART_INF_F);

    // depth-2 preload (row-clamped duplicates; harmless)
    float2 s0[4], s1[4];
    {
        const float* p = fp + ys * WF;
        #pragma unroll
        for (int g = 0; g < 4; ++g) s0[g] = *(const float2*)(p + g * 2 * CS);
        const int h1 = min(ys + 1, hlast);
        const float* q = fp + h1 * WF;
        #pragma unroll
        for (int g = 0; g < 4; ++g) s1[g] = *(const float2*)(q + g * 2 * CS);
    }
    float2 m[4];
    #pragma unroll
    for (int g = 0; g < 4; ++g) m[g] = NEG2;

    const int T = hlast - ys + 1;
    for (int k = 0; k < T; k += 2) {
        #pragma unroll
        for (int j = 0; j < 2; ++j) {
            const int h = ys + k + j;
            float2 a[4];
            #pragma unroll
            for (int g = 0; g < 4; ++g) a[g] = (j == 0) ? s0[g] : s1[g];
            // refill this stage with row h+2 (clamped) — before the close branch
            {
                const int hn = min(h + 2, hlast);
                const float* p = fp + hn * WF;
                #pragma unroll
                for (int g = 0; g < 4; ++g) {
                    float2 t = *(const float2*)(p + g * 2 * CS);
                    if (j == 0) s0[g] = t; else s1[g] = t;
                }
            }
            #pragma unroll
            for (int g = 0; g < 4; ++g) {
                m[g].x = fmaxf(m[g].x, a[g].x);
                m[g].y = fmaxf(m[g].y, a[g].y);
            }

            if (ph < PH && h == hcut - 1) {    // warp-uniform; may close SEVERAL bins
                do {
                    const int p2 = 2 * ln;
                    #pragma unroll
                    for (int g = 0; g < 4; ++g)
                        *(float2*)&rm[warpId][2 * g + hw][ph][p2] = m[g];
                    // next bin starts at h (overlap) or h+1 (disjoint)
                    const int hs_next = ys + (int)floorf((float)(ph + 1) * binh);
                    const bool ov = (hs_next <= h);
                    #pragma unroll
                    for (int g = 0; g < 4; ++g) {
                        m[g].x = ov ? a[g].x : -CUDART_INF_F;
                        m[g].y = ov ? a[g].y : -CUDART_INF_F;
                    }
                    ph++;
                    hcut = ys + (int)ceilf((float)(ph + 1) * binh);
                } while (ph < PH && h == hcut - 1);
            }
        }
    }
    __syncwarp();

    // ---- phase 2: column max per (ph,pw) bin (positions offset by d) ----
    const size_t obase = ((size_t)n * C + c0) * (PH * PW);
    #pragma unroll
    for (int rep = 0; rep < 2; ++rep) {
        int pp = rep * 32 + lane;
        if (pp < PH * PW) {
            int phh = pp / PW;
            int pw  = pp - phh * PW;
            int wsl = (int)floorf((float)pw * binw);          // local cols, >= 0
            int wel = (int)ceilf((float)(pw + 1) * binw);     // may reach roiw+1
            const int wl = wel - 1;                           // <= roiw (covered)
            // two channel groups of 4 to bound live registers
            #pragma unroll
            for (int cgg = 0; cgg < 2; ++cgg) {
                float v0 = -CUDART_INF_F, v1 = -CUDART_INF_F;
                float v2 = -CUDART_INF_F, v3 = -CUDART_INF_F;
                #pragma unroll
                for (int j = 0; j < 6; ++j) {                 // col-bin extent <= 6
                    const int idx = d + min(wsl + j, wl);
                    v0 = fmaxf(v0, rm[warpId][4 * cgg + 0][phh][idx]);
                    v1 = fmaxf(v1, rm[warpId][4 * cgg + 1][phh][idx]);
                    v2 = fmaxf(v2, rm[warpId][4 * cgg + 2][phh][idx]);
                    v3 = fmaxf(v3, rm[warpId][4 * cgg + 3][phh][idx]);
                }
                const size_t ob = obase + (size_t)(4 * cgg) * (PH * PW) + pp;
                out[ob]                  = v0;
                out[ob + (PH * PW)]      = v1;
                out[ob + 2 * (PH * PW)]  = v2;
                out[ob + 3 * (PH * PW)]  = v3;
            }
        }
    }
}

extern "C" void kernel_launch(void* const* d_in, const int* in_sizes, int n_in,
                              void* d_out, int out_size) {
    const float* feat   = (const float*)d_in[0];
    const float* rois   = (const float*)d_in[1];
    const int*   stride = (const int*)d_in[2];
    float*       out    = (float*)d_out;

    const int N = in_sizes[1] / 5;
    const int C = out_size / (N * PH * PW);        // 256
    const int gpr = C / CPW;                       // 32
    const int total_warps = N * gpr;               // 16384
    const int blocks = (total_warps + WARPS - 1) / WARPS;   // 4096

    roipool_c8_kernel<<<blocks, 32 * WARPS>>>(feat, rois, stride, out, C, gpr);
}

// round 13
// speedup vs baseline: 1.1113x; 1.1113x over previous
#include <cuda_runtime.h>
#include <math_constants.h>

// RoIPool, warp-cooperative, single-pass row scan, float2 lanes, unroll-4
// pipeline (R10 structure) + warp-uniform dynamic phase-2 depth + predicated STS.
// feature [B,C,152,152] f32, rois [N,5] f32, out [N,C,7,7] f32.
// One warp = (roi n, 4 consecutive channels).
//   Columns: xs0 = xs & ~1, d = xs - xs0. Half-warp hw covers channels c0+hw
//   (reg A) and c0+2+hw (reg B); lane ln loads float2 at pair min(ln, plim),
//   plim = (d+roiw)>>1: every position phase 2 reads (d..d+roiw) is covered;
//   tail lanes duplicate the last pair (same cache lines, harmless for max).
//   Rows: scan ys..hlast = ys+ceil(7*binh)-1 once; bins tile with <=1-row
//   overlap; several bins may close on one row (do/while). 4-stage register
//   ring, prefetch distance 4, refills clamped to hlast (duplicates never
//   stored: all 7 bins close by h=hlast, ph<7 guards the close).
// Bin sizes = roiX * fl(1/7) (reciprocal multiply) to match XLA bit-exactly.

#define PH 7
#define PW 7
#define HF 152
#define WF 152
#define CPW 4
#define WARPS 8

__global__ __launch_bounds__(256) void roipool_f2j_kernel(
    const float* __restrict__ feat,
    const float* __restrict__ rois,
    const int* __restrict__ stride_p,
    float* __restrict__ out,
    int C, int gpr)
{
    __shared__ __align__(16) float rm[WARPS][CPW][PH][34];

    int si = *stride_p;
    float stride_f = (si > 0 && si <= 65536) ? (float)si : __int_as_float(si);
    const float scale = 1.0f / stride_f;

    const int warpId = threadIdx.x >> 5;
    const int lane   = threadIdx.x & 31;
    const int hw = lane >> 4;          // half-warp -> sub-channel
    const int ln = lane & 15;          // lane within half-warp -> column pair
    const int wg = blockIdx.x * WARPS + warpId;
    const int n  = wg / gpr;
    const int cg = wg - n * gpr;
    const int c0 = cg * CPW;

    const float* r = rois + n * 5;
    const int b  = (int)r[0];
    const int xs = (int)rintf(r[1] * scale);   // round-half-even, matches jnp.round
    const int ys = (int)rintf(r[2] * scale);
    const int xe = (int)rintf(r[3] * scale);
    const int ye = (int)rintf(r[4] * scale);
    const int roih = max(ye - ys + 1, 1);
    const int roiw = max(xe - xs + 1, 1);
    const float binh = (float)roih * (1.0f / 7.0f);   // reciprocal multiply (bit-exact)
    const float binw = (float)roiw * (1.0f / 7.0f);

    const int xs0 = xs & ~1;
    const int d   = xs - xs0;
    const int plim = (d + roiw) >> 1;           // last pair phase 2 can touch
    const int c2   = xs0 + 2 * min(ln, plim);   // in-bounds (<= 150)
    const bool wact = (ln <= plim);             // lane's pair is readable by phase 2

    const size_t cs = (size_t)HF * WF;
    const float* fA = feat + ((size_t)(b * C + c0 + hw)) * cs + c2;  // ch c0+hw
    const float* fB = fA + 2 * cs;                                    // ch c0+2+hw

    const int hlast = ys + (int)ceilf(7.0f * binh) - 1;   // <= ye+1 <= 151
    int ph   = 0;
    int hcut = ys + (int)ceilf(binh);                     // hend of bin 0

    // 4-stage preload (row-clamped duplicates; harmless)
    float2 sA[4], sB[4];
    #pragma unroll
    for (int j = 0; j < 4; ++j) {
        const int hj = min(ys + j, hlast);
        sA[j] = *(const float2*)(fA + hj * WF);
        sB[j] = *(const float2*)(fB + hj * WF);
    }
    float2 mA = make_float2(-CUDART_INF_F, -CUDART_INF_F);
    float2 mB = make_float2(-CUDART_INF_F, -CUDART_INF_F);

    const int T = hlast - ys + 1;
    for (int k = 0; k < T; k += 4) {
        #pragma unroll
        for (int j = 0; j < 4; ++j) {
            const int h = ys + k + j;
            const float2 aA = sA[j];
            const float2 aB = sB[j];
            // refill stage with row h+4 (clamped) — issued before the close branch
            const int hn = min(h + 4, hlast);
            sA[j] = *(const float2*)(fA + hn * WF);
            sB[j] = *(const float2*)(fB + hn * WF);

            mA.x = fmaxf(mA.x, aA.x);  mA.y = fmaxf(mA.y, aA.y);
            mB.x = fmaxf(mB.x, aB.x);  mB.y = fmaxf(mB.y, aB.y);

            if (ph < PH && h == hcut - 1) {    // warp-uniform; may close SEVERAL bins
                do {
                    if (wact) {                 // tail pairs never read back
                        const int p = 2 * ln;
                        *(float2*)&rm[warpId][hw][ph][p]     = mA;
                        *(float2*)&rm[warpId][2 + hw][ph][p] = mB;
                    }
                    // next bin starts at h (overlap) or h+1 (disjoint)
                    const int hs_next = ys + (int)floorf((float)(ph + 1) * binh);
                    const bool ov = (hs_next <= h);
                    mA.x = ov ? aA.x : -CUDART_INF_F;
                    mA.y = ov ? aA.y : -CUDART_INF_F;
                    mB.x = ov ? aB.x : -CUDART_INF_F;
                    mB.y = ov ? aB.y : -CUDART_INF_F;
                    ph++;
                    hcut = ys + (int)ceilf((float)(ph + 1) * binh);
                } while (ph < PH && h == hcut - 1);
            }
        }
    }
    __syncwarp();

    // ---- phase 2: column max per (ph,pw) bin (positions offset by d) ----
    // Bin width wel-wsl <= ceil(binw)+1 -> warp-uniform J <= 6; extra
    // iterations clamp to wl (duplicate broadcast reads, harmless).
    const int J = min((int)ceilf(binw) + 1, 6);
    const size_t obase = ((size_t)n * C + c0) * (PH * PW);
    #pragma unroll
    for (int rep = 0; rep < 2; ++rep) {
        int pp = rep * 32 + lane;
        if (pp < PH * PW) {
            int phh = pp / PW;
            int pw  = pp - phh * PW;
            int wsl = (int)floorf((float)pw * binw);          // local cols, >= 0
            int wel = (int)ceilf((float)(pw + 1) * binw);     // may reach roiw+1
            const int wl = wel - 1;                           // <= roiw (covered)
            float v0 = -CUDART_INF_F, v1 = -CUDART_INF_F;
            float v2 = -CUDART_INF_F, v3 = -CUDART_INF_F;
            for (int j = 0; j < J; ++j) {                     // warp-uniform trip
                const int idx = d + min(wsl + j, wl);
                v0 = fmaxf(v0, rm[warpId][0][phh][idx]);
                v1 = fmaxf(v1, rm[warpId][1][phh][idx]);
                v2 = fmaxf(v2, rm[warpId][2][phh][idx]);
                v3 = fmaxf(v3, rm[warpId][3][phh][idx]);
            }
            out[obase + pp]                 = v0;
            out[obase + (PH * PW) + pp]     = v1;
            out[obase + 2 * (PH * PW) + pp] = v2;
            out[obase + 3 * (PH * PW) + pp] = v3;
        }
    }
}

extern "C" void kernel_launch(void* const* d_in, const int* in_sizes, int n_in,
                              void* d_out, int out_size) {
    const float* feat   = (const float*)d_in[0];
    const float* rois   = (const float*)d_in[1];
    const int*   stride = (const int*)d_in[2];
    float*       out    = (float*)d_out;

    const int N = in_sizes[1] / 5;
    const int C = out_size / (N * PH * PW);        // 256
    const int gpr = C / CPW;                       // 64
    const int total_warps = N * gpr;               // 32768
    const int blocks = (total_warps + WARPS - 1) / WARPS;   // 4096

    roipool_f2j_kernel<<<blocks, 32 * WARPS>>>(feat, rois, stride, out, C, gpr);
}

// round 14
// speedup vs baseline: 1.2302x; 1.1070x over previous
#include <cuda_runtime.h>
#include <math_constants.h>

// RoIPool, warp-cooperative, single-pass row scan, float2 lanes, unroll-4
// pipeline with TAIL-SPLIT (final chunk issues no refills), warp-uniform
// dynamic phase-2 depth, predicated STS.
// feature [B,C,152,152] f32, rois [N,5] f32, out [N,C,7,7] f32.
// One warp = (roi n, 4 consecutive channels).
//   Columns: xs0 = xs & ~1, d = xs - xs0. Half-warp hw covers channels c0+hw
//   (reg A) and c0+2+hw (reg B); lane ln loads float2 at pair min(ln, plim),
//   plim = (d+roiw)>>1: every position phase 2 reads (d..d+roiw) is covered;
//   tail lanes duplicate the last pair (same cache lines, harmless for max).
//   Rows: scan ys..hlast = ys+ceil(7*binh)-1 once; bins tile with <=1-row
//   overlap; several bins may close on one row (do/while). 4-stage ring,
//   prefetch distance 4. Main chunks run while k+4 < T (their refills feed
//   later rows); the tail chunk consumes the last <=4 stages refill-free.
//   Stage j always holds row min(ys+k+j, hlast); tail rows past hlast are
//   clamped duplicates that cannot close a bin (hcut <= hlast+1, ph<7 guard).
// Bin sizes = roiX * fl(1/7) (reciprocal multiply) to match XLA bit-exactly.

#define PH 7
#define PW 7
#define HF 152
#define WF 152
#define CPW 4
#define WARPS 8

__global__ __launch_bounds__(256) void roipool_f2t_kernel(
    const float* __restrict__ feat,
    const float* __restrict__ rois,
    const int* __restrict__ stride_p,
    float* __restrict__ out,
    int C, int gpr)
{
    __shared__ __align__(16) float rm[WARPS][CPW][PH][34];

    int si = *stride_p;
    float stride_f = (si > 0 && si <= 65536) ? (float)si : __int_as_float(si);
    const float scale = 1.0f / stride_f;

    const int warpId = threadIdx.x >> 5;
    const int lane   = threadIdx.x & 31;
    const int hw = lane >> 4;          // half-warp -> sub-channel
    const int ln = lane & 15;          // lane within half-warp -> column pair
    const int wg = blockIdx.x * WARPS + warpId;
    const int n  = wg / gpr;
    const int cg = wg - n * gpr;
    const int c0 = cg * CPW;

    const float* r = rois + n * 5;
    const int b  = (int)r[0];
    const int xs = (int)rintf(r[1] * scale);   // round-half-even, matches jnp.round
    const int ys = (int)rintf(r[2] * scale);
    const int xe = (int)rintf(r[3] * scale);
    const int ye = (int)rintf(r[4] * scale);
    const int roih = max(ye - ys + 1, 1);
    const int roiw = max(xe - xs + 1, 1);
    const float binh = (float)roih * (1.0f / 7.0f);   // reciprocal multiply (bit-exact)
    const float binw = (float)roiw * (1.0f / 7.0f);

    const int xs0 = xs & ~1;
    const int d   = xs - xs0;
    const int plim = (d + roiw) >> 1;           // last pair phase 2 can touch
    const int c2   = xs0 + 2 * min(ln, plim);   // in-bounds (<= 150)
    const bool wact = (ln <= plim);             // lane's pair is readable by phase 2

    const size_t cs = (size_t)HF * WF;
    const float* fA = feat + ((size_t)(b * C + c0 + hw)) * cs + c2;  // ch c0+hw
    const float* fB = fA + 2 * cs;                                    // ch c0+2+hw

    const int hlast = ys + (int)ceilf(7.0f * binh) - 1;   // <= ye+1 <= 151
    int ph   = 0;
    int hcut = ys + (int)ceilf(binh);                     // hend of bin 0

    // 4-stage preload (row-clamped duplicates; harmless)
    float2 sA[4], sB[4];
    #pragma unroll
    for (int j = 0; j < 4; ++j) {
        const int hj = min(ys + j, hlast);
        sA[j] = *(const float2*)(fA + hj * WF);
        sB[j] = *(const float2*)(fB + hj * WF);
    }
    float2 mA = make_float2(-CUDART_INF_F, -CUDART_INF_F);
    float2 mB = make_float2(-CUDART_INF_F, -CUDART_INF_F);

    const int T = hlast - ys + 1;
    int k = 0;
    // ---- main chunks: refill needed (rows k+4..k+7 will be consumed) ----
    for (; k + 4 < T; k += 4) {
        #pragma unroll
        for (int j = 0; j < 4; ++j) {
            const int h = ys + k + j;                  // real row (< hlast+1)
            const float2 aA = sA[j];
            const float2 aB = sB[j];
            const int hn = min(h + 4, hlast);          // clamped refill
            sA[j] = *(const float2*)(fA + hn * WF);
            sB[j] = *(const float2*)(fB + hn * WF);

            mA.x = fmaxf(mA.x, aA.x);  mA.y = fmaxf(mA.y, aA.y);
            mB.x = fmaxf(mB.x, aB.x);  mB.y = fmaxf(mB.y, aB.y);

            if (ph < PH && h == hcut - 1) {    // warp-uniform; may close SEVERAL bins
                do {
                    if (wact) {
                        const int p = 2 * ln;
                        *(float2*)&rm[warpId][hw][ph][p]     = mA;
                        *(float2*)&rm[warpId][2 + hw][ph][p] = mB;
                    }
                    const int hs_next = ys + (int)floorf((float)(ph + 1) * binh);
                    const bool ov = (hs_next <= h);
                    mA.x = ov ? aA.x : -CUDART_INF_F;
                    mA.y = ov ? aA.y : -CUDART_INF_F;
                    mB.x = ov ? aB.x : -CUDART_INF_F;
                    mB.y = ov ? aB.y : -CUDART_INF_F;
                    ph++;
                    hcut = ys + (int)ceilf((float)(ph + 1) * binh);
                } while (ph < PH && h == hcut - 1);
            }
        }
    }
    // ---- tail chunk: consume remaining stages, NO refills ----
    #pragma unroll
    for (int j = 0; j < 4; ++j) {
        const int h = ys + k + j;            // may exceed hlast: dupes, cannot close
        const float2 aA = sA[j];
        const float2 aB = sB[j];

        mA.x = fmaxf(mA.x, aA.x);  mA.y = fmaxf(mA.y, aA.y);
        mB.x = fmaxf(mB.x, aB.x);  mB.y = fmaxf(mB.y, aB.y);

        if (ph < PH && h == hcut - 1) {
            do {
                if (wact) {
                    const int p = 2 * ln;
                    *(float2*)&rm[warpId][hw][ph][p]     = mA;
                    *(float2*)&rm[warpId][2 + hw][ph][p] = mB;
                }
                const int hs_next = ys + (int)floorf((float)(ph + 1) * binh);
                const bool ov = (hs_next <= h);
                mA.x = ov ? aA.x : -CUDART_INF_F;
                mA.y = ov ? aA.y : -CUDART_INF_F;
                mB.x = ov ? aB.x : -CUDART_INF_F;
                mB.y = ov ? aB.y : -CUDART_INF_F;
                ph++;
                hcut = ys + (int)ceilf((float)(ph + 1) * binh);
            } while (ph < PH && h == hcut - 1);
        }
    }
    __syncwarp();

    // ---- phase 2: column max per (ph,pw) bin (positions offset by d) ----
    // Warp-uniform depth J; extra iterations clamp to wl (broadcast dupes).
    const int J = min((int)ceilf(binw) + 1, 6);
    const size_t obase = ((size_t)n * C + c0) * (PH * PW);
    #pragma unroll
    for (int rep = 0; rep < 2; ++rep) {
        int pp = rep * 32 + lane;
        if (pp < PH * PW) {
            int phh = pp / PW;
            int pw  = pp - phh * PW;
            int wsl = (int)floorf((float)pw * binw);          // local cols, >= 0
            int wel = (int)ceilf((float)(pw + 1) * binw);     // may reach roiw+1
            const int wl = wel - 1;                           // <= roiw (covered)
            float v0 = -CUDART_INF_F, v1 = -CUDART_INF_F;
            float v2 = -CUDART_INF_F, v3 = -CUDART_INF_F;
            for (int j = 0; j < J; ++j) {                     // warp-uniform trip
                const int idx = d + min(wsl + j, wl);
                v0 = fmaxf(v0, rm[warpId][0][phh][idx]);
                v1 = fmaxf(v1, rm[warpId][1][phh][idx]);
                v2 = fmaxf(v2, rm[warpId][2][phh][idx]);
                v3 = fmaxf(v3, rm[warpId][3][phh][idx]);
            }
            out[obase + pp]                 = v0;
            out[obase + (PH * PW) + pp]     = v1;
            out[obase + 2 * (PH * PW) + pp] = v2;
            out[obase + 3 * (PH * PW) + pp] = v3;
        }
    }
}

extern "C" void kernel_launch(void* const* d_in, const int* in_sizes, int n_in,
                              void* d_out, int out_size) {
    const float* feat   = (const float*)d_in[0];
    const float* rois   = (const float*)d_in[1];
    const int*   stride = (const int*)d_in[2];
    float*       out    = (float*)d_out;

    const int N = in_sizes[1] / 5;
    const int C = out_size / (N * PH * PW);        // 256
    const int gpr = C / CPW;                       // 64
    const int total_warps = N * gpr;               // 32768
    const int blocks = (total_warps + WARPS - 1) / WARPS;   // 4096

    roipool_f2t_kernel<<<blocks, 32 * WARPS>>>(feat, rois, stride, out, C, gpr);
}